// round 8
// baseline (speedup 1.0000x reference)
#include <cuda_runtime.h>
#include <cstdint>

// ============================================================================
// SpecAttn via mma.sync tf32 (HMMA). R7: R6 skeleton (128x128 tile, 128 thr,
// 2 CTAs/SM, LDS.64 k-relabel, fused softmax) with a DEEPER pipeline:
// BK=16, ST=4 (3-chunk prefetch, ~72KB in flight) to hide L2/DRAM latency.
// ============================================================================

#define BM 128
#define BN 128
#define BK 16
#define ST 4
#define ROWF 24                        // 16 + 8 pad; conflict-free per 16-lane phase
#define TILE_F (BM * ROWF)             // 3072 floats
#define STAGE_F (2 * TILE_F)           // A + B per stage = 6144 floats
#define STAGE_BYTES (STAGE_F * 4)      // 24576 B
#define SMEM_BYTES (ST * STAGE_BYTES)  // 98304 B (96KB) -> 2 CTAs/SM

#define MSROWS 16384                   // B*S

// ---------------- scratch (device globals; no allocations) ------------------
__device__ float g_xc [8L*2048*1024];
__device__ float g_q  [8L*2048*1024];
__device__ float g_k  [8L*2048*1024];
__device__ float g_v  [8L*2048*1024];
__device__ float g_vt [8L*2048*1024];
__device__ float g_ctx[8L*2048*1024];
__device__ float g_e  [8L*2048*2048];
__device__ float g_wqT[1024L*1024];
__device__ float g_wkT[1024L*1024];
__device__ float g_wvT[1024L*1024];
__device__ float g_woT[1024L*1024];
__device__ float g_rsp[32L*MSROWS];    // per-(bx,nwarp) row-sum partials
__device__ float g_rs [MSROWS];        // reduced row sums

// ---------------- helpers ----------------------------------------------------
__device__ __forceinline__ uint32_t smem_u32(const void* p) {
    uint32_t a;
    asm("{ .reg .u64 t; cvta.to.shared.u64 t, %1; cvt.u32.u64 %0, t; }" : "=r"(a) : "l"(p));
    return a;
}
__device__ __forceinline__ float to_tf32(float x) {
    uint32_t u;
    asm("cvt.rna.tf32.f32 %0, %1;" : "=r"(u) : "f"(x));
    return __uint_as_float(u);
}
__device__ __forceinline__ void mma_tf32(float* c, const uint32_t* a, const uint32_t* b) {
    asm volatile(
        "mma.sync.aligned.m16n8k8.row.col.f32.tf32.tf32.f32 "
        "{%0,%1,%2,%3},{%4,%5,%6,%7},{%8,%9},{%0,%1,%2,%3};"
        : "+f"(c[0]), "+f"(c[1]), "+f"(c[2]), "+f"(c[3])
        : "r"(a[0]), "r"(a[1]), "r"(a[2]), "r"(a[3]), "r"(b[0]), "r"(b[1]));
}
__device__ __forceinline__ uint32_t fbits(float x) { return __float_as_uint(x); }

// ============================================================================
// tf32 GEMM: C[z] = f( alpha * A[z] @ B[z]^T + bias )
//   MODE 0: plain.  MODE 1: f=exp, emit row-sum partials.  MODE 2: scale rows
//   by 1/rowsum.  A: [M,K] rm.  B: [N,K] rm.  M,N mult 128, K mult 16.
// grid = (N/BN, M/BM, Z), block = 128 (4 warps, 2x2 grid, 64x64 warp tiles).
// ============================================================================
template <bool HAS_BIAS, bool CVT_OUT, int MODE>
__global__ __launch_bounds__(128, 2)
void tf32_gemm(const float* __restrict__ A, const float* __restrict__ Bm,
               const float* __restrict__ bias, float* __restrict__ C,
               int K, int N, long sA, long sB, long sC, float alpha,
               float* __restrict__ rsum, float* __restrict__ rsp,
               long rsStride)
{
    extern __shared__ float smf[];
    const uint32_t sbase = smem_u32(smf);
    const int tid = threadIdx.x;

    A  += (long)blockIdx.z * sA;
    Bm += (long)blockIdx.z * sB;
    C  += (long)blockIdx.z * sC;
    const long rowBase = (long)blockIdx.y * BM;
    const long colBase = (long)blockIdx.x * BN;
    const long rsBase  = (long)blockIdx.z * rsStride + rowBase;

    // ---- global->smem mapping: thread covers rows (tid>>2)+32i, seg tid&3 ----
    const int lr = tid >> 2;           // 0..31
    const int ls = tid & 3;            // 16B segment within 64B row
    const uint32_t off0 = (uint32_t)(lr * ROWF + ls * 4) * 4;
    const float* Ag = A  + (rowBase + lr) * (long)K + ls * 4;
    const float* Bg = Bm + (colBase + lr) * (long)K + ls * 4;

    const int NT = K >> 4;

#define LOAD_STAGE(sbuf, kt) do {                                              \
    const uint32_t st_ = sbase + (uint32_t)(sbuf) * STAGE_BYTES;               \
    const uint32_t bt_ = st_ + TILE_F * 4;                                     \
    const long ko_ = (long)(kt) * BK;                                          \
    _Pragma("unroll")                                                          \
    for (int i_ = 0; i_ < 4; i_++) {                                           \
        asm volatile("cp.async.cg.shared.global [%0],[%1],16;"                 \
            :: "r"(st_ + off0 + (uint32_t)i_ * (32 * ROWF * 4)),               \
               "l"(Ag + ko_ + (long)32 * i_ * K) : "memory");                  \
        asm volatile("cp.async.cg.shared.global [%0],[%1],16;"                 \
            :: "r"(bt_ + off0 + (uint32_t)i_ * (32 * ROWF * 4)),               \
               "l"(Bg + ko_ + (long)32 * i_ * K) : "memory");                  \
    }                                                                          \
    asm volatile("cp.async.commit_group;" ::: "memory");                       \
} while (0)

    // prologue: 3 stages in flight
    LOAD_STAGE(0, 0);
    LOAD_STAGE(1, 1);
    LOAD_STAGE(2, 2);

    // ---- warp tiling: 2x2 warp grid, 64x64 per warp ----
    const int warp = tid >> 5, lane = tid & 31;
    const int grp = lane >> 2, tg = lane & 3;
    const int mbase = (warp & 1) * 64;
    const int nbase = (warp >> 1) * 64;

    float acc[4][8][4];
    #pragma unroll
    for (int mt = 0; mt < 4; mt++)
        #pragma unroll
        for (int nt = 0; nt < 8; nt++)
            #pragma unroll
            for (int j = 0; j < 4; j++) acc[mt][nt][j] = 0.f;

    for (int t = 0; t < NT; ++t) {
        // tail-safe wait: all groups older than the 2 most recent are done
        if (t < NT - 2)      asm volatile("cp.async.wait_group 2;" ::: "memory");
        else if (t == NT - 2) asm volatile("cp.async.wait_group 1;" ::: "memory");
        else                 asm volatile("cp.async.wait_group 0;" ::: "memory");
        __syncthreads();
        if (t + 3 < NT) {
            int sb_ = t + 3;
            sb_ &= (ST - 1);               // ST=4 power of two
            LOAD_STAGE(sb_, t + 3);
        }

        const float* sAt = smf + (t & (ST - 1)) * STAGE_F;
        const float* sBt = sAt + TILE_F;

        #pragma unroll
        for (int k8 = 0; k8 < BK; k8 += 8) {
            // k-slot relabel: MMA slot tg <- smem col k8+2tg, slot tg+4 <- k8+2tg+1
            uint32_t a[4][4], b[8][2];
            #pragma unroll
            for (int mt = 0; mt < 4; mt++) {
                const int r = mbase + mt * 16 + grp;
                const float2 v0 = *(const float2*)(sAt + r * ROWF + k8 + 2 * tg);
                const float2 v1 = *(const float2*)(sAt + (r + 8) * ROWF + k8 + 2 * tg);
                a[mt][0] = fbits(v0.x); a[mt][2] = fbits(v0.y);
                a[mt][1] = fbits(v1.x); a[mt][3] = fbits(v1.y);
            }
            #pragma unroll
            for (int nt = 0; nt < 8; nt++) {
                const float2 w = *(const float2*)(sBt + (nbase + nt * 8 + grp) * ROWF + k8 + 2 * tg);
                b[nt][0] = fbits(w.x); b[nt][1] = fbits(w.y);
            }
            #pragma unroll
            for (int mt = 0; mt < 4; mt++)
                #pragma unroll
                for (int nt = 0; nt < 8; nt++)
                    mma_tf32(acc[mt][nt], a[mt], b[nt]);
        }
    }

    // ---- epilogue (mt-outer so MODE 1/2 can work per-row) ----
    float2 bv[8];
    #pragma unroll
    for (int nt = 0; nt < 8; nt++) {
        if (HAS_BIAS) bv[nt] = *(const float2*)(bias + colBase + nbase + nt * 8 + tg * 2);
        else          bv[nt] = make_float2(0.f, 0.f);
    }

    #pragma unroll
    for (int mt = 0; mt < 4; mt++) {
        const int rloc = mbase + mt * 16 + grp;      // local row (and +8)
        const long r0 = rowBase + rloc;
        float inv0 = 1.f, inv1 = 1.f;
        if (MODE == 2) {
            inv0 = 1.f / rsum[rsBase + rloc];
            inv1 = 1.f / rsum[rsBase + rloc + 8];
        }
        float rs0 = 0.f, rs1 = 0.f;
        #pragma unroll
        for (int nt = 0; nt < 8; nt++) {
            const long col = colBase + nbase + nt * 8 + tg * 2;
            float o0 = acc[mt][nt][0] * alpha + bv[nt].x;
            float o1 = acc[mt][nt][1] * alpha + bv[nt].y;
            float o2 = acc[mt][nt][2] * alpha + bv[nt].x;
            float o3 = acc[mt][nt][3] * alpha + bv[nt].y;
            if (MODE == 1) {
                o0 = __expf(o0); o1 = __expf(o1);
                o2 = __expf(o2); o3 = __expf(o3);
                rs0 += o0 + o1;  rs1 += o2 + o3;
            }
            if (MODE == 2) {
                o0 *= inv0; o1 *= inv0; o2 *= inv1; o3 *= inv1;
            }
            if (CVT_OUT) {
                o0 = to_tf32(o0); o1 = to_tf32(o1);
                o2 = to_tf32(o2); o3 = to_tf32(o3);
            }
            *(float2*)(C + r0 * N + col)       = make_float2(o0, o1);
            *(float2*)(C + (r0 + 8) * N + col) = make_float2(o2, o3);
        }
        if (MODE == 1) {
            rs0 += __shfl_xor_sync(~0u, rs0, 1);
            rs0 += __shfl_xor_sync(~0u, rs0, 2);
            rs1 += __shfl_xor_sync(~0u, rs1, 1);
            rs1 += __shfl_xor_sync(~0u, rs1, 2);
            if (tg == 0) {
                const long slot = ((long)blockIdx.x * 2 + (warp >> 1)) * MSROWS + rsBase + rloc;
                rsp[slot]     = rs0;
                rsp[slot + 8] = rs1;
            }
        }
    }
#undef LOAD_STAGE
}

// ============================================================================
// reduce 32 row-sum partials per row -> rowsum.
// ============================================================================
__global__ __launch_bounds__(256)
void rowsum_reduce(const float* __restrict__ rsp, float* __restrict__ rsum)
{
    const int i = blockIdx.x * 256 + threadIdx.x;
    float s = 0.f;
    #pragma unroll
    for (int j = 0; j < 32; j++) s += rsp[(long)j * MSROWS + i];
    rsum[i] = s;
}

// ============================================================================
// transpose + tf32 round: dst[c][r] = tf32(src[r][c]).  grid(cols/32, rows/32, Z)
// ============================================================================
__global__ __launch_bounds__(256)
void transpose_kernel(const float* __restrict__ src, float* __restrict__ dst,
                      int rows, int cols)
{
    __shared__ float tile[32][33];
    const long zoff = (long)blockIdx.z * rows * (long)cols;
    src += zoff; dst += zoff;
    const int c0 = blockIdx.x * 32, r0 = blockIdx.y * 32;
    const int tx = threadIdx.x, ty = threadIdx.y;
    #pragma unroll
    for (int i = ty; i < 32; i += 8)
        tile[i][tx] = to_tf32(src[(long)(r0 + i) * cols + c0 + tx]);
    __syncthreads();
    #pragma unroll
    for (int i = ty; i < 32; i += 8)
        dst[(long)(c0 + i) * rows + r0 + tx] = tile[tx][i];
}

// elementwise tf32 round (for x)
__global__ __launch_bounds__(256)
void cvt_kernel(const float4* __restrict__ in, float4* __restrict__ out, long n4)
{
    long i = blockIdx.x * 256L + threadIdx.x;
    const long stride = gridDim.x * 256L;
    for (; i < n4; i += stride) {
        float4 v = in[i];
        v.x = to_tf32(v.x); v.y = to_tf32(v.y);
        v.z = to_tf32(v.z); v.w = to_tf32(v.w);
        out[i] = v;
    }
}

// ============================================================================
extern "C" void kernel_launch(void* const* d_in, const int* in_sizes, int n_in,
                              void* d_out, int out_size)
{
    (void)in_sizes; (void)n_in; (void)out_size;
    const float* x  = (const float*)d_in[0];
    const float* wq = (const float*)d_in[1];
    const float* bq = (const float*)d_in[2];
    const float* wk = (const float*)d_in[3];
    const float* bk = (const float*)d_in[4];
    const float* wv = (const float*)d_in[5];
    const float* bv = (const float*)d_in[6];
    const float* wo = (const float*)d_in[7];
    const float* bo = (const float*)d_in[8];
    float* out = (float*)d_out;

    float *xc, *q, *k, *v, *vt, *ctx, *e, *wqT, *wkT, *wvT, *woT, *rsp, *rs;
    cudaGetSymbolAddress((void**)&xc,  g_xc);
    cudaGetSymbolAddress((void**)&q,   g_q);
    cudaGetSymbolAddress((void**)&k,   g_k);
    cudaGetSymbolAddress((void**)&v,   g_v);
    cudaGetSymbolAddress((void**)&vt,  g_vt);
    cudaGetSymbolAddress((void**)&ctx, g_ctx);
    cudaGetSymbolAddress((void**)&e,   g_e);
    cudaGetSymbolAddress((void**)&wqT, g_wqT);
    cudaGetSymbolAddress((void**)&wkT, g_wkT);
    cudaGetSymbolAddress((void**)&wvT, g_wvT);
    cudaGetSymbolAddress((void**)&woT, g_woT);
    cudaGetSymbolAddress((void**)&rsp, g_rsp);
    cudaGetSymbolAddress((void**)&rs,  g_rs);

    cudaFuncSetAttribute(tf32_gemm<true,  true,  0>, cudaFuncAttributeMaxDynamicSharedMemorySize, SMEM_BYTES);
    cudaFuncSetAttribute(tf32_gemm<true,  false, 0>, cudaFuncAttributeMaxDynamicSharedMemorySize, SMEM_BYTES);
    cudaFuncSetAttribute(tf32_gemm<false, true,  1>, cudaFuncAttributeMaxDynamicSharedMemorySize, SMEM_BYTES);
    cudaFuncSetAttribute(tf32_gemm<false, true,  2>, cudaFuncAttributeMaxDynamicSharedMemorySize, SMEM_BYTES);

    const int Bsz = 8, S = 2048, H = 1024;
    const int MS = Bsz * S;                 // 16384
    const float scale = 0.03125f;           // 1/sqrt(1024)

    // pre-round x to tf32
    cvt_kernel<<<1024, 256>>>((const float4*)x, (float4*)xc, (long)MS * H / 4);

    dim3 tb(32, 8);
    transpose_kernel<<<dim3(32, 32, 1), tb>>>(wq, wqT, H, H);
    transpose_kernel<<<dim3(32, 32, 1), tb>>>(wk, wkT, H, H);
    transpose_kernel<<<dim3(32, 32, 1), tb>>>(wv, wvT, H, H);
    transpose_kernel<<<dim3(32, 32, 1), tb>>>(wo, woT, H, H);

    dim3 blk(128);
    dim3 gProj(H / BN, MS / BM, 1);   // (8, 128)

    // QKV projections (outputs rounded to tf32 for the next GEMMs)
    tf32_gemm<true, true, 0><<<gProj, blk, SMEM_BYTES>>>(
        xc, wqT, bq, q, H, H, 0, 0, 0, 1.f, nullptr, nullptr, 0);
    tf32_gemm<true, true, 0><<<gProj, blk, SMEM_BYTES>>>(
        xc, wkT, bk, k, H, H, 0, 0, 0, 1.f, nullptr, nullptr, 0);
    tf32_gemm<true, true, 0><<<gProj, blk, SMEM_BYTES>>>(
        xc, wvT, bv, v, H, H, 0, 0, 0, 1.f, nullptr, nullptr, 0);

    // V transpose per batch: [S,H] -> [H,S]
    transpose_kernel<<<dim3(H / 32, S / 32, Bsz), tb>>>(v, vt, S, H);

    // Energy + exp fused: P = exp(scale * Q @ K^T), row-sum partials emitted.
    tf32_gemm<false, true, 1><<<dim3(S / BN, S / BM, Bsz), blk, SMEM_BYTES>>>(
        q, k, nullptr, e, H, S, (long)S * H, (long)S * H, (long)S * S, scale,
        nullptr, rsp, (long)S);

    rowsum_reduce<<<MS / 256, 256>>>(rsp, rs);

    // Context: ctx = (P @ V) / rowsum
    tf32_gemm<false, true, 2><<<dim3(H / BN, S / BM, Bsz), blk, SMEM_BYTES>>>(
        e, vt, nullptr, ctx, S, H, (long)S * S, (long)H * S, (long)S * H, 1.f,
        rs, nullptr, (long)S);

    // Output projection
    tf32_gemm<true, false, 0><<<gProj, blk, SMEM_BYTES>>>(
        ctx, woT, bo, out, H, H, 0, 0, 0, 1.f, nullptr, nullptr, 0);
}

// round 9
// speedup vs baseline: 1.1300x; 1.1300x over previous
#include <cuda_runtime.h>
#include <cstdint>

// ============================================================================
// SpecAttn via mma.sync tf32 (HMMA). R8: R6 GEMM skeleton exactly (128x128,
// BK=32, ST=2, 128 thr, 2 CTAs/SM, LDS.64 k-relabel, fused softmax), with
// overhead removal: V produced directly transposed (row-bias GEMM), Q+K
// projections merged into one N=2048 GEMM (ld-aware), fewer passes/launches.
// ============================================================================

#define BM 128
#define BN 128
#define BK 32
#define ST 2
#define ROWF 40                        // 32 + 8 pad; ROWF%32==8 -> LDS.64 conflict-free
#define TILE_F (BM * ROWF)             // 5120 floats
#define STAGE_F (2 * TILE_F)
#define SMEM_BYTES (ST * STAGE_F * 4)  // 81920 B

#define MSROWS 16384                   // B*S

// ---------------- scratch (device globals; no allocations) ------------------
__device__ float g_xc  [8L*2048*1024];
__device__ float g_qk  [16384L*2048];   // [B*S, 2048]: cols 0-1023 = Q, 1024+ = K
__device__ float g_vt  [8L*1024*2048];  // per batch [H, S]
__device__ float g_ctx [8L*2048*1024];
__device__ float g_e   [8L*2048*2048];
__device__ float g_wqkT[2048L*1024];    // rows 0-1023 wq^T, 1024+ wk^T
__device__ float g_wvT [1024L*1024];
__device__ float g_woT [1024L*1024];
__device__ float g_bqk [2048];
__device__ float g_rsp [32L*MSROWS];    // per-(bx,nwarp) row-sum partials
__device__ float g_rs  [MSROWS];        // reduced row sums

// ---------------- helpers ----------------------------------------------------
__device__ __forceinline__ uint32_t smem_u32(const void* p) {
    uint32_t a;
    asm("{ .reg .u64 t; cvta.to.shared.u64 t, %1; cvt.u32.u64 %0, t; }" : "=r"(a) : "l"(p));
    return a;
}
__device__ __forceinline__ float to_tf32(float x) {
    uint32_t u;
    asm("cvt.rna.tf32.f32 %0, %1;" : "=r"(u) : "f"(x));
    return __uint_as_float(u);
}
__device__ __forceinline__ void mma_tf32(float* c, const uint32_t* a, const uint32_t* b) {
    asm volatile(
        "mma.sync.aligned.m16n8k8.row.col.f32.tf32.tf32.f32 "
        "{%0,%1,%2,%3},{%4,%5,%6,%7},{%8,%9},{%0,%1,%2,%3};"
        : "+f"(c[0]), "+f"(c[1]), "+f"(c[2]), "+f"(c[3])
        : "r"(a[0]), "r"(a[1]), "r"(a[2]), "r"(a[3]), "r"(b[0]), "r"(b[1]));
}
__device__ __forceinline__ uint32_t fbits(float x) { return __float_as_uint(x); }

// ============================================================================
// tf32 GEMM: C[z] = f( alpha * A[z] @ B[z]^T + bias )
//   BIAS: 0 none, 1 per-column, 2 per-row.
//   MODE: 0 plain, 1 f=exp + row-sum partials, 2 scale rows by 1/rowsum.
//   A: [M,K] rm (ld ldA).  B: [N,K] rm (ld ldB).  C: ld ldC.
// grid = (N/BN, M/BM, Z), block = 128 (4 warps, 2x2 grid, 64x64 warp tiles).
// ============================================================================
template <int BIAS, bool CVT_OUT, int MODE>
__global__ __launch_bounds__(128, 2)
void tf32_gemm(const float* __restrict__ A, const float* __restrict__ Bm,
               const float* __restrict__ bias, float* __restrict__ C,
               int K, int ldA, int ldB, int ldC,
               long sA, long sB, long sC, float alpha,
               const float* __restrict__ rsum, float* __restrict__ rsp,
               long rsStride)
{
    extern __shared__ float smf[];
    const uint32_t sbase = smem_u32(smf);
    const int tid = threadIdx.x;

    A  += (long)blockIdx.z * sA;
    Bm += (long)blockIdx.z * sB;
    C  += (long)blockIdx.z * sC;
    const long rowBase = (long)blockIdx.y * BM;
    const long colBase = (long)blockIdx.x * BN;
    const long rsBase  = (long)blockIdx.z * rsStride + rowBase;

    // ---- global->smem mapping: thread covers rows (tid>>3)+16i, seg tid&7 ----
    const int lr = tid >> 3;           // 0..15
    const int ls = tid & 7;            // 16B segment within 128B row
    const uint32_t off0 = (uint32_t)(lr * ROWF + ls * 4) * 4;
    const float* Ag = A  + (rowBase + lr) * (long)ldA + ls * 4;
    const float* Bg = Bm + (colBase + lr) * (long)ldB + ls * 4;

    const int NT = K >> 5;

#define LOAD_STAGE(sbuf, kt) do {                                              \
    const uint32_t st_ = sbase + (uint32_t)(sbuf) * (STAGE_F * 4);             \
    const uint32_t bt_ = st_ + TILE_F * 4;                                     \
    const long ko_ = (long)(kt) * BK;                                          \
    _Pragma("unroll")                                                          \
    for (int i_ = 0; i_ < 8; i_++) {                                           \
        asm volatile("cp.async.cg.shared.global [%0],[%1],16;"                 \
            :: "r"(st_ + off0 + (uint32_t)i_ * (16 * ROWF * 4)),               \
               "l"(Ag + ko_ + (long)16 * i_ * ldA) : "memory");                \
        asm volatile("cp.async.cg.shared.global [%0],[%1],16;"                 \
            :: "r"(bt_ + off0 + (uint32_t)i_ * (16 * ROWF * 4)),               \
               "l"(Bg + ko_ + (long)16 * i_ * ldB) : "memory");                \
    }                                                                          \
    asm volatile("cp.async.commit_group;" ::: "memory");                       \
} while (0)

    // prologue
    LOAD_STAGE(0, 0);

    // ---- warp tiling: 2x2 warp grid, 64x64 per warp ----
    const int warp = tid >> 5, lane = tid & 31;
    const int grp = lane >> 2, tg = lane & 3;
    const int mbase = (warp & 1) * 64;
    const int nbase = (warp >> 1) * 64;

    float acc[4][8][4];
    #pragma unroll
    for (int mt = 0; mt < 4; mt++)
        #pragma unroll
        for (int nt = 0; nt < 8; nt++)
            #pragma unroll
            for (int j = 0; j < 4; j++) acc[mt][nt][j] = 0.f;

    for (int t = 0; t < NT; ++t) {
        asm volatile("cp.async.wait_group 0;" ::: "memory");
        __syncthreads();
        if (t + 1 < NT) LOAD_STAGE((t + 1) & 1, t + 1);

        const float* sAt = smf + (t & 1) * STAGE_F;
        const float* sBt = sAt + TILE_F;

        #pragma unroll
        for (int k8 = 0; k8 < BK; k8 += 8) {
            // k-slot relabel: MMA slot tg <- smem col k8+2tg, slot tg+4 <- k8+2tg+1
            uint32_t a[4][4], b[8][2];
            #pragma unroll
            for (int mt = 0; mt < 4; mt++) {
                const int r = mbase + mt * 16 + grp;
                const float2 v0 = *(const float2*)(sAt + r * ROWF + k8 + 2 * tg);
                const float2 v1 = *(const float2*)(sAt + (r + 8) * ROWF + k8 + 2 * tg);
                a[mt][0] = fbits(v0.x); a[mt][2] = fbits(v0.y);
                a[mt][1] = fbits(v1.x); a[mt][3] = fbits(v1.y);
            }
            #pragma unroll
            for (int nt = 0; nt < 8; nt++) {
                const float2 w = *(const float2*)(sBt + (nbase + nt * 8 + grp) * ROWF + k8 + 2 * tg);
                b[nt][0] = fbits(w.x); b[nt][1] = fbits(w.y);
            }
            #pragma unroll
            for (int mt = 0; mt < 4; mt++)
                #pragma unroll
                for (int nt = 0; nt < 8; nt++)
                    mma_tf32(acc[mt][nt], a[mt], b[nt]);
        }
    }

    // ---- epilogue (mt-outer so MODE 1/2 and row-bias work per-row) ----
    float2 bv[8];
    #pragma unroll
    for (int nt = 0; nt < 8; nt++) {
        if (BIAS == 1) bv[nt] = *(const float2*)(bias + colBase + nbase + nt * 8 + tg * 2);
        else           bv[nt] = make_float2(0.f, 0.f);
    }

    #pragma unroll
    for (int mt = 0; mt < 4; mt++) {
        const int rloc = mbase + mt * 16 + grp;      // local row (and +8)
        const long r0 = rowBase + rloc;
        float rb0 = 0.f, rb1 = 0.f;
        if (BIAS == 2) {
            rb0 = bias[r0];
            rb1 = bias[r0 + 8];
        }
        float inv0 = 1.f, inv1 = 1.f;
        if (MODE == 2) {
            inv0 = 1.f / rsum[rsBase + rloc];
            inv1 = 1.f / rsum[rsBase + rloc + 8];
        }
        float rs0 = 0.f, rs1 = 0.f;
        #pragma unroll
        for (int nt = 0; nt < 8; nt++) {
            const long col = colBase + nbase + nt * 8 + tg * 2;
            float o0 = acc[mt][nt][0] * alpha + bv[nt].x + rb0;
            float o1 = acc[mt][nt][1] * alpha + bv[nt].y + rb0;
            float o2 = acc[mt][nt][2] * alpha + bv[nt].x + rb1;
            float o3 = acc[mt][nt][3] * alpha + bv[nt].y + rb1;
            if (MODE == 1) {
                o0 = __expf(o0); o1 = __expf(o1);
                o2 = __expf(o2); o3 = __expf(o3);
                rs0 += o0 + o1;  rs1 += o2 + o3;
            }
            if (MODE == 2) {
                o0 *= inv0; o1 *= inv0; o2 *= inv1; o3 *= inv1;
            }
            if (CVT_OUT) {
                o0 = to_tf32(o0); o1 = to_tf32(o1);
                o2 = to_tf32(o2); o3 = to_tf32(o3);
            }
            *(float2*)(C + r0 * (long)ldC + col)       = make_float2(o0, o1);
            *(float2*)(C + (r0 + 8) * (long)ldC + col) = make_float2(o2, o3);
        }
        if (MODE == 1) {
            rs0 += __shfl_xor_sync(~0u, rs0, 1);
            rs0 += __shfl_xor_sync(~0u, rs0, 2);
            rs1 += __shfl_xor_sync(~0u, rs1, 1);
            rs1 += __shfl_xor_sync(~0u, rs1, 2);
            if (tg == 0) {
                const long slot = ((long)blockIdx.x * 2 + (warp >> 1)) * MSROWS + rsBase + rloc;
                rsp[slot]     = rs0;
                rsp[slot + 8] = rs1;
            }
        }
    }
#undef LOAD_STAGE
}

// ============================================================================
// reduce 32 row-sum partials per row -> rowsum.
// ============================================================================
__global__ __launch_bounds__(256)
void rowsum_reduce(const float* __restrict__ rsp, float* __restrict__ rsum)
{
    const int i = blockIdx.x * 256 + threadIdx.x;
    float s = 0.f;
    #pragma unroll
    for (int j = 0; j < 32; j++) s += rsp[(long)j * MSROWS + i];
    rsum[i] = s;
}

// ============================================================================
// transpose + tf32 round: dst[c][r] = tf32(src[r][c]).  grid(cols/32, rows/32)
// ============================================================================
__global__ __launch_bounds__(256)
void transpose_kernel(const float* __restrict__ src, float* __restrict__ dst,
                      int rows, int cols)
{
    __shared__ float tile[32][33];
    const int c0 = blockIdx.x * 32, r0 = blockIdx.y * 32;
    const int tx = threadIdx.x, ty = threadIdx.y;
    #pragma unroll
    for (int i = ty; i < 32; i += 8)
        tile[i][tx] = to_tf32(src[(long)(r0 + i) * cols + c0 + tx]);
    __syncthreads();
    #pragma unroll
    for (int i = ty; i < 32; i += 8)
        dst[(long)(c0 + i) * rows + r0 + tx] = tile[tx][i];
}

// elementwise tf32 round (for x)
__global__ __launch_bounds__(256)
void cvt_kernel(const float4* __restrict__ in, float4* __restrict__ out, long n4)
{
    long i = blockIdx.x * 256L + threadIdx.x;
    const long stride = gridDim.x * 256L;
    for (; i < n4; i += stride) {
        float4 v = in[i];
        v.x = to_tf32(v.x); v.y = to_tf32(v.y);
        v.z = to_tf32(v.z); v.w = to_tf32(v.w);
        out[i] = v;
    }
}

// ============================================================================
extern "C" void kernel_launch(void* const* d_in, const int* in_sizes, int n_in,
                              void* d_out, int out_size)
{
    (void)in_sizes; (void)n_in; (void)out_size;
    const float* x  = (const float*)d_in[0];
    const float* wq = (const float*)d_in[1];
    const float* bq = (const float*)d_in[2];
    const float* wk = (const float*)d_in[3];
    const float* bk = (const float*)d_in[4];
    const float* wv = (const float*)d_in[5];
    const float* bv = (const float*)d_in[6];
    const float* wo = (const float*)d_in[7];
    const float* bo = (const float*)d_in[8];
    float* out = (float*)d_out;

    float *xc, *qk, *vt, *ctx, *e, *wqkT, *wvT, *woT, *bqk, *rsp, *rs;
    cudaGetSymbolAddress((void**)&xc,   g_xc);
    cudaGetSymbolAddress((void**)&qk,   g_qk);
    cudaGetSymbolAddress((void**)&vt,   g_vt);
    cudaGetSymbolAddress((void**)&ctx,  g_ctx);
    cudaGetSymbolAddress((void**)&e,    g_e);
    cudaGetSymbolAddress((void**)&wqkT, g_wqkT);
    cudaGetSymbolAddress((void**)&wvT,  g_wvT);
    cudaGetSymbolAddress((void**)&woT,  g_woT);
    cudaGetSymbolAddress((void**)&bqk,  g_bqk);
    cudaGetSymbolAddress((void**)&rsp,  g_rsp);
    cudaGetSymbolAddress((void**)&rs,   g_rs);

    cudaFuncSetAttribute(tf32_gemm<1, true,  0>, cudaFuncAttributeMaxDynamicSharedMemorySize, SMEM_BYTES);
    cudaFuncSetAttribute(tf32_gemm<2, true,  0>, cudaFuncAttributeMaxDynamicSharedMemorySize, SMEM_BYTES);
    cudaFuncSetAttribute(tf32_gemm<1, false, 0>, cudaFuncAttributeMaxDynamicSharedMemorySize, SMEM_BYTES);
    cudaFuncSetAttribute(tf32_gemm<0, true,  1>, cudaFuncAttributeMaxDynamicSharedMemorySize, SMEM_BYTES);
    cudaFuncSetAttribute(tf32_gemm<0, true,  2>, cudaFuncAttributeMaxDynamicSharedMemorySize, SMEM_BYTES);

    const int Bsz = 8, S = 2048, H = 1024;
    const int MS = Bsz * S;                 // 16384
    const float scale = 0.03125f;           // 1/sqrt(1024)

    // pre-round x to tf32
    cvt_kernel<<<1024, 256>>>((const float4*)x, (float4*)xc, (long)MS * H / 4);

    dim3 tb(32, 8);
    // wqkT rows 0-1023 = wq^T, rows 1024-2047 = wk^T
    transpose_kernel<<<dim3(32, 32), tb>>>(wq, wqkT, H, H);
    transpose_kernel<<<dim3(32, 32), tb>>>(wk, wqkT + (long)H * H, H, H);
    transpose_kernel<<<dim3(32, 32), tb>>>(wv, wvT, H, H);
    transpose_kernel<<<dim3(32, 32), tb>>>(wo, woT, H, H);
    // bias concat (async D2D copies are graph-capturable)
    cudaMemcpyAsync(bqk,        bq, H * sizeof(float), cudaMemcpyDeviceToDevice);
    cudaMemcpyAsync(bqk + H,    bk, H * sizeof(float), cudaMemcpyDeviceToDevice);

    dim3 blk(128);

    // Q+K projection, merged: qk[MS, 2048] = xc @ wqkT^T + bqk
    tf32_gemm<1, true, 0><<<dim3(2 * H / BN, MS / BM, 1), blk, SMEM_BYTES>>>(
        xc, wqkT, bqk, qk, H, H, H, 2 * H, 0, 0, 0, 1.f, nullptr, nullptr, 0);

    // V, produced transposed: vt[b] (H x S) = wvT @ x[b]^T + bv (row bias)
    tf32_gemm<2, true, 0><<<dim3(S / BN, H / BM, Bsz), blk, SMEM_BYTES>>>(
        wvT, xc, bv, vt, H, H, H, S,
        0, (long)S * H, (long)H * S, 1.f, nullptr, nullptr, 0);

    // Energy + exp fused: P = exp(scale * Q @ K^T), row-sum partials emitted.
    tf32_gemm<0, true, 1><<<dim3(S / BN, S / BM, Bsz), blk, SMEM_BYTES>>>(
        qk, qk + H, nullptr, e, H, 2 * H, 2 * H, S,
        (long)S * 2 * H, (long)S * 2 * H, (long)S * S, scale,
        nullptr, rsp, (long)S);

    rowsum_reduce<<<MS / 256, 256>>>(rsp, rs);

    // Context: ctx = (P @ V) / rowsum   (B = vt [H, S], K-major over S)
    tf32_gemm<0, true, 2><<<dim3(H / BN, S / BM, Bsz), blk, SMEM_BYTES>>>(
        e, vt, nullptr, ctx, S, S, S, H,
        (long)S * S, (long)H * S, (long)S * H, 1.f, rs, nullptr, (long)S);

    // Output projection
    tf32_gemm<1, false, 0><<<dim3(H / BN, MS / BM, 1), blk, SMEM_BYTES>>>(
        ctx, woT, bo, out, H, H, H, H, 0, 0, 0, 1.f, nullptr, nullptr, 0);
}